// round 15
// baseline (speedup 1.0000x reference)
#include <cuda_runtime.h>
#include <cuda_bf16.h>
#include <cstdint>

#define Bb 2
#define Ss 4096
#define HIDN 2048
#define Hh 16
#define HKVn 8
#define Dd 128
#define Mm 256
#define NCn 32

// ---------------- scratch -----------------------------------------------------
__device__ float g_q[(size_t)Bb * Hh * Ss * Dd];
__device__ float g_k[(size_t)Bb * HKVn * Ss * Dd];
__device__ float g_v[(size_t)Bb * HKVn * Ss * Dd];
__device__ float g_phik[(size_t)Bb * HKVn * Ss * Mm];
__device__ float g_kv[(size_t)Bb * HKVn * NCn * Mm * Dd];   // [bh, c, d, m]
__device__ float g_ksum[(size_t)Bb * HKVn * NCn * Mm];
__device__ float g_part[4096];
__device__ float g_zmax;

// bf16 hi/lo operands
__device__ __nv_bfloat16 g_ah[16777216], g_al[16777216];
__device__ __nv_bfloat16 g_wqh[4194304], g_wql[4194304];
__device__ __nv_bfloat16 g_wkh[2097152], g_wkl[2097152];
__device__ __nv_bfloat16 g_wvh[2097152], g_wvl[2097152];
__device__ __nv_bfloat16 g_woh[4194304], g_wol[4194304];
__device__ __nv_bfloat16 g_projh[32768], g_projl[32768];
__device__ __nv_bfloat16 g_phiqh[33554432], g_phiql[33554432];
__device__ __nv_bfloat16 g_phikh[16777216], g_phikl[16777216];
__device__ __nv_bfloat16 g_vth[8388608],  g_vtl[8388608];      // [bh, d, s]
__device__ __nv_bfloat16 g_kvth[16777216], g_kvtl[16777216];   // [bh, c, d, m]

// ---------------- helpers -----------------------------------------------------
__device__ __forceinline__ uint32_t smem_u32(const void* p) {
    uint32_t a;
    asm("{ .reg .u64 t; cvta.to.shared.u64 t, %1; cvt.u32.u64 %0, t; }" : "=r"(a) : "l"(p));
    return a;
}
__device__ __forceinline__ void cp16(uint32_t dst, const void* src) {
    asm volatile("cp.async.cg.shared.global [%0], [%1], 16;" :: "r"(dst), "l"(src));
}
__device__ __forceinline__ void cp_commit() { asm volatile("cp.async.commit_group;"); }
__device__ __forceinline__ void cp_wait1()  { asm volatile("cp.async.wait_group 1;"); }
__device__ __forceinline__ void cp_wait0()  { asm volatile("cp.async.wait_group 0;"); }

__device__ __forceinline__ void ldmx4(uint32_t* r, uint32_t addr) {
    asm volatile("ldmatrix.sync.aligned.m8n8.x4.shared.b16 {%0,%1,%2,%3}, [%4];"
                 : "=r"(r[0]), "=r"(r[1]), "=r"(r[2]), "=r"(r[3]) : "r"(addr));
}
__device__ __forceinline__ void mma16816(float* c, const uint32_t* a, const uint32_t* b) {
    asm volatile(
        "mma.sync.aligned.m16n8k16.row.col.f32.bf16.bf16.f32 "
        "{%0,%1,%2,%3},{%4,%5,%6,%7},{%8,%9},{%0,%1,%2,%3};"
        : "+f"(c[0]), "+f"(c[1]), "+f"(c[2]), "+f"(c[3])
        : "r"(a[0]), "r"(a[1]), "r"(a[2]), "r"(a[3]), "r"(b[0]), "r"(b[1]));
}
__device__ __forceinline__ void bsplit(float v, __nv_bfloat16& h, __nv_bfloat16& l) {
    h = __float2bfloat16(v);
    l = __float2bfloat16(v - __bfloat162float(h));
}

// ---------------- fp32 -> bf16 hi/lo split -----------------------------------
__global__ void split_kernel(const float* __restrict__ x, __nv_bfloat16* __restrict__ hi,
                             __nv_bfloat16* __restrict__ lo, int n4)
{
    int i = blockIdx.x * 256 + threadIdx.x;
    if (i < n4) {
        float4 v = ((const float4*)x)[i];
        __nv_bfloat16 h0, h1, h2, h3, l0, l1, l2, l3;
        bsplit(v.x, h0, l0); bsplit(v.y, h1, l1);
        bsplit(v.z, h2, l2); bsplit(v.w, h3, l3);
        ushort4 hh, ll;
        hh.x = __bfloat16_as_ushort(h0); hh.y = __bfloat16_as_ushort(h1);
        hh.z = __bfloat16_as_ushort(h2); hh.w = __bfloat16_as_ushort(h3);
        ll.x = __bfloat16_as_ushort(l0); ll.y = __bfloat16_as_ushort(l1);
        ll.z = __bfloat16_as_ushort(l2); ll.w = __bfloat16_as_ushort(l3);
        ((ushort4*)hi)[i] = hh;
        ((ushort4*)lo)[i] = ll;
    }
}

// ---------------- HMMA bf16x3 GEMM body, CTA tile 128x128 (R10 proven) --------
#define STG_BYTES 40960
#define TILE_BYTES 10240
__device__ __forceinline__ void gemm_body(
    char* smem,
    const __nv_bfloat16* Ah, const __nv_bfloat16* Al,
    const __nv_bfloat16* Wh, const __nv_bfloat16* Wl,
    float* C, int N, int mode, int NH, int row0, int col0, int vtrans)
{
    const uint32_t sb = smem_u32(smem);
    const int t = threadIdx.x, lane = t & 31, wid = t >> 5;
    const int wm = wid >> 2, wn = wid & 3;

    const __nv_bfloat16* gA[2] = { Ah + (size_t)row0 * 2048, Al + (size_t)row0 * 2048 };
    const __nv_bfloat16* gB[2] = { Wh + (size_t)col0 * 2048, Wl + (size_t)col0 * 2048 };

    auto issue = [&](int s, int kc) {
        uint32_t base = sb + s * STG_BYTES;
#pragma unroll
        for (int idx = t; idx < 2048; idx += 256) {
            int tile = idx >> 9;
            int rem = idx & 511;
            int r = rem >> 2, c = rem & 3;
            const __nv_bfloat16* src =
                (tile < 2 ? gA[tile] : gB[tile - 2]) + (size_t)r * 2048 + kc * 32 + c * 8;
            cp16(base + tile * TILE_BYTES + r * 80 + c * 16, src);
        }
        cp_commit();
    };

    float acc[4][4][4];
#pragma unroll
    for (int i = 0; i < 4; i++)
#pragma unroll
        for (int j = 0; j < 4; j++)
#pragma unroll
            for (int k = 0; k < 4; k++) acc[i][j][k] = 0.f;

    issue(0, 0);
    issue(1, 1);

    const int arow = wm * 64 + (lane & 15);
    const int acol = (lane >> 4) * 16;
    const int brow = wn * 32 + (lane & 7) + ((lane >> 4) & 1) * 8;
    const int bcol = ((lane >> 3) & 1) * 16;

    for (int kc = 0; kc < 64; kc++) {
        cp_wait1();
        __syncthreads();
        uint32_t base = sb + (kc & 1) * STG_BYTES;
        uint32_t aH = base, aL = base + TILE_BYTES;
        uint32_t bH = base + 2 * TILE_BYTES, bL = base + 3 * TILE_BYTES;
#pragma unroll
        for (int ks = 0; ks < 2; ks++) {
            uint32_t kb = ks * 32;
            uint32_t ah[4][4], al[4][4], bh[4][2], bl[4][2];
#pragma unroll
            for (int i = 0; i < 4; i++) {
                uint32_t off = (uint32_t)(arow + i * 16) * 80 + kb + acol;
                ldmx4(ah[i], aH + off);
                ldmx4(al[i], aL + off);
            }
#pragma unroll
            for (int nt = 0; nt < 2; nt++) {
                uint32_t off = (uint32_t)(brow + nt * 16) * 80 + kb + bcol;
                uint32_t rh[4], rl[4];
                ldmx4(rh, bH + off);
                ldmx4(rl, bL + off);
                bh[nt * 2][0] = rh[0]; bh[nt * 2][1] = rh[1];
                bh[nt * 2 + 1][0] = rh[2]; bh[nt * 2 + 1][1] = rh[3];
                bl[nt * 2][0] = rl[0]; bl[nt * 2][1] = rl[1];
                bl[nt * 2 + 1][0] = rl[2]; bl[nt * 2 + 1][1] = rl[3];
            }
#pragma unroll
            for (int i = 0; i < 4; i++)
#pragma unroll
                for (int j = 0; j < 4; j++) {
                    mma16816(acc[i][j], ah[i], bh[j]);
                    mma16816(acc[i][j], ah[i], bl[j]);
                    mma16816(acc[i][j], al[i], bh[j]);
                }
        }
        __syncthreads();
        if (kc + 2 < 64) issue(kc & 1, kc + 2);
        else cp_commit();
    }

#pragma unroll
    for (int i = 0; i < 4; i++) {
        int m = wm * 64 + i * 16 + (lane >> 2);
#pragma unroll
        for (int j = 0; j < 4; j++) {
            int n = wn * 32 + j * 8 + (lane & 3) * 2;
#pragma unroll
            for (int half = 0; half < 2; half++) {
                int mr = m + half * 8;
                float2 v;
                v.x = acc[i][j][half * 2 + 0];
                v.y = acc[i][j][half * 2 + 1];
                if (mode == 0) {
                    *(float2*)(C + (size_t)(row0 + mr) * N + col0 + n) = v;
                } else {
                    int b = (row0 + mr) >> 12, srow = (row0 + mr) & 4095;
                    int h = col0 >> 7;
                    *(float2*)(C + ((((size_t)b * NH + h) * 4096 + srow) << 7) + n) = v;
                }
            }
        }
    }

    if (vtrans) {
        __syncthreads();
        float* Ts = (float*)smem;
#pragma unroll
        for (int i = 0; i < 4; i++) {
            int m = wm * 64 + i * 16 + (lane >> 2);
#pragma unroll
            for (int j = 0; j < 4; j++) {
                int n = wn * 32 + j * 8 + (lane & 3) * 2;
#pragma unroll
                for (int half = 0; half < 2; half++) {
                    int mr = m + half * 8;
                    Ts[mr * 133 + n]     = acc[i][j][half * 2 + 0];
                    Ts[mr * 133 + n + 1] = acc[i][j][half * 2 + 1];
                }
            }
        }
        __syncthreads();
        int b = row0 >> 12, s0 = row0 & 4095;
        int kvh = col0 >> 7;
        size_t vbase = ((size_t)(b * HKVn + kvh)) * 128 * 4096;
        for (int idx = t; idx < 16384; idx += 256) {
            int d = idx >> 7, ss = idx & 127;
            float val = Ts[ss * 133 + d];
            __nv_bfloat16 h, l; bsplit(val, h, l);
            size_t o = vbase + (size_t)d * 4096 + s0 + ss;
            g_vth[o] = h; g_vtl[o] = l;
        }
    }
}

// O projection kernel
__global__ void __launch_bounds__(256, 2)
hmma_gemm(const __nv_bfloat16* __restrict__ Ah, const __nv_bfloat16* __restrict__ Al,
          const __nv_bfloat16* __restrict__ Wh, const __nv_bfloat16* __restrict__ Wl,
          float* __restrict__ C, int N, int mode, int NH)
{
    extern __shared__ char smem[];
    gemm_body(smem, Ah, Al, Wh, Wl, C, N, mode, NH, blockIdx.y * 128, blockIdx.x * 128, 0);
}

// fused QKV projection
__global__ void __launch_bounds__(256, 2)
hmma_qkv()
{
    extern __shared__ char smem[];
    int bx = blockIdx.x;
    const __nv_bfloat16 *Wh, *Wl;
    float* C;
    int NH, col0, vtrans;
    if (bx < 16)      { Wh = g_wqh; Wl = g_wql; C = g_q; NH = 16; col0 = bx * 128; vtrans = 0; }
    else if (bx < 24) { Wh = g_wkh; Wl = g_wkl; C = g_k; NH = 8;  col0 = (bx - 16) * 128; vtrans = 0; }
    else              { Wh = g_wvh; Wl = g_wvl; C = g_v; NH = 8;  col0 = (bx - 24) * 128; vtrans = 1; }
    gemm_body(smem, g_ah, g_al, Wh, Wl, C, 0, 1, NH, blockIdx.y * 128, col0, vtrans);
}

// ---------------- feature map: HMMA, rope fused, q+k merged, 2 proj passes ----
#define FM_SMEM 106496
#define FMP 272
__global__ void __launch_bounds__(256, 2)
featmap_hmma(const float* __restrict__ cosp, const float* __restrict__ sinp)
{
    extern __shared__ char smem[];
    const uint32_t sb = smem_u32(smem);
    const int t = threadIdx.x, lane = t & 31, wid = t >> 5;
    const int wm = wid >> 2, wn = wid & 3;
    const int bid = blockIdx.x;
    const int isq = (bid < 2048);
    const float* X = isq ? g_q : g_k;
    const int NH = isq ? 16 : 8;
    const size_t row0 = (size_t)(isq ? bid : bid - 2048) * 64;

    ushort* XH = (ushort*)(smem);
    ushort* XL = (ushort*)(smem + 17408);
    float* maxpart = (float*)(smem + 104448);
    float* rowred  = (float*)(smem + 105472);
    float* sq      = (float*)(smem + 105728);

    auto issueP = [&](int p) {
#pragma unroll
        for (int idx = t; idx < 4096; idx += 256) {
            int tile = idx >> 11, rem = idx & 2047;
            int r = rem >> 4, v = rem & 15;
            const __nv_bfloat16* src = (tile ? g_projl : g_projh) + (p * 128 + r) * 128 + v * 8;
            cp16(sb + 34816 + tile * 34816 + r * FMP + v * 16, src);
        }
        cp_commit();
    };
    issueP(0);

    const float sc = 0.29730177875068026f;
    for (int i = t; i < 64 * 64; i += 256) {
        int r = i >> 6, d = i & 63;
        size_t row = row0 + r;
        int b = (int)(row / ((size_t)NH * 4096));
        int s = (int)(row & 4095);
        size_t base = row * 128;
        float x1 = X[base + d], x2 = X[base + d + 64];
        size_t cb = (((size_t)b * 4096 + s) << 7);
        float c1 = cosp[cb + d],      s1v = sinp[cb + d];
        float c2 = cosp[cb + d + 64], s2v = sinp[cb + d + 64];
        float y1 = (x1 * c1 - x2 * s1v) * sc;
        float y2 = (x2 * c2 + x1 * s2v) * sc;
        __nv_bfloat16 h, l;
        bsplit(y1, h, l);
        XH[r * 136 + d] = __bfloat16_as_ushort(h);
        XL[r * 136 + d] = __bfloat16_as_ushort(l);
        bsplit(y2, h, l);
        XH[r * 136 + d + 64] = __bfloat16_as_ushort(h);
        XL[r * 136 + d + 64] = __bfloat16_as_ushort(l);
    }
    __syncthreads();

    {
        int r = t >> 2, qq = t & 3;
        float p = 0.f;
        for (int dd = 0; dd < 32; dd++) {
            int d = qq * 32 + dd;
            float v = __bfloat162float(__ushort_as_bfloat16(XH[r * 136 + d])) +
                      __bfloat162float(__ushort_as_bfloat16(XL[r * 136 + d]));
            p = fmaf(v, v, p);
        }
        p += __shfl_xor_sync(0xffffffffu, p, 1);
        p += __shfl_xor_sync(0xffffffffu, p, 2);
        if (qq == 0) sq[r] = 0.5f * p;
    }

    float acc[2][8][4];
#pragma unroll
    for (int i = 0; i < 2; i++)
#pragma unroll
        for (int j = 0; j < 8; j++)
#pragma unroll
            for (int k = 0; k < 4; k++) acc[i][j][k] = 0.f;

    const int arow = wm * 32 + (lane & 15);
    const int acolB = (lane >> 4) * 16;
    const int brow = wn * 32 + (lane & 7) + ((lane >> 4) & 1) * 8;
    const int bcolB = ((lane >> 3) & 1) * 16;
    const uint32_t xh0 = sb, xl0 = sb + 17408;
    const uint32_t ph0 = sb + 34816, pl0 = sb + 69632;

#pragma unroll
    for (int p = 0; p < 2; p++) {
        cp_wait0();
        __syncthreads();
#pragma unroll
        for (int ks = 0; ks < 8; ks++) {
            uint32_t kb = ks * 32;
            uint32_t ah[2][4], al[2][4], bh[4][2], bl[4][2];
#pragma unroll
            for (int i = 0; i < 2; i++) {
                uint32_t off = (uint32_t)(arow + i * 16) * FMP + kb + acolB;
                ldmx4(ah[i], xh0 + off);
                ldmx4(al[i], xl0 + off);
            }
#pragma unroll
            for (int nt = 0; nt < 2; nt++) {
                uint32_t off = (uint32_t)(brow + nt * 16) * FMP + kb + bcolB;
                uint32_t rh[4], rl[4];
                ldmx4(rh, ph0 + off);
                ldmx4(rl, pl0 + off);
                bh[nt * 2][0] = rh[0]; bh[nt * 2][1] = rh[1];
                bh[nt * 2 + 1][0] = rh[2]; bh[nt * 2 + 1][1] = rh[3];
                bl[nt * 2][0] = rl[0]; bl[nt * 2][1] = rl[1];
                bl[nt * 2 + 1][0] = rl[2]; bl[nt * 2 + 1][1] = rl[3];
            }
#pragma unroll
            for (int i = 0; i < 2; i++)
#pragma unroll
                for (int jj = 0; jj < 4; jj++) {
                    mma16816(acc[i][p * 4 + jj], ah[i], bh[jj]);
                    mma16816(acc[i][p * 4 + jj], ah[i], bl[jj]);
                    mma16816(acc[i][p * 4 + jj], al[i], bh[jj]);
                }
        }
        if (p == 0) {
            __syncthreads();
            issueP(1);
        }
    }

#pragma unroll
    for (int i = 0; i < 2; i++) {
        int r1 = wm * 32 + i * 16 + (lane >> 2);
        float s1 = sq[r1], s2 = sq[r1 + 8];
#pragma unroll
        for (int j = 0; j < 8; j++) {
            acc[i][j][0] -= s1; acc[i][j][1] -= s1;
            acc[i][j][2] -= s2; acc[i][j][3] -= s2;
        }
    }

    if (isq) {
#pragma unroll
        for (int i = 0; i < 2; i++) {
            int r1 = wm * 32 + i * 16 + (lane >> 2);
            float m1 = -1e30f, m2 = -1e30f;
#pragma unroll
            for (int j = 0; j < 8; j++) {
                m1 = fmaxf(m1, fmaxf(acc[i][j][0], acc[i][j][1]));
                m2 = fmaxf(m2, fmaxf(acc[i][j][2], acc[i][j][3]));
            }
            m1 = fmaxf(m1, __shfl_xor_sync(0xffffffffu, m1, 1));
            m1 = fmaxf(m1, __shfl_xor_sync(0xffffffffu, m1, 2));
            m2 = fmaxf(m2, __shfl_xor_sync(0xffffffffu, m2, 1));
            m2 = fmaxf(m2, __shfl_xor_sync(0xffffffffu, m2, 2));
            if ((lane & 3) == 0) {
                maxpart[wn * 64 + r1] = m1;
                maxpart[wn * 64 + r1 + 8] = m2;
            }
        }
        __syncthreads();
        if (t < 64)
            rowred[t] = fmaxf(fmaxf(maxpart[t], maxpart[64 + t]),
                              fmaxf(maxpart[128 + t], maxpart[192 + t]));
        __syncthreads();
#pragma unroll
        for (int i = 0; i < 2; i++) {
            int r1 = wm * 32 + i * 16 + (lane >> 2);
            float mx1 = rowred[r1], mx2 = rowred[r1 + 8];
            size_t ro1 = (row0 + r1) * 256, ro2 = (row0 + r1 + 8) * 256;
#pragma unroll
            for (int j = 0; j < 8; j++) {
                int n0 = (j >> 2) * 128 + wn * 32 + (j & 3) * 8 + (lane & 3) * 2;
                __nv_bfloat16 h0, l0, h1, l1;
                float v0 = expf(acc[i][j][0] - mx1) * 0.0625f + 1e-6f;
                float v1 = expf(acc[i][j][1] - mx1) * 0.0625f + 1e-6f;
                bsplit(v0, h0, l0); bsplit(v1, h1, l1);
                *(ushort2*)(g_phiqh + ro1 + n0) = make_ushort2(__bfloat16_as_ushort(h0), __bfloat16_as_ushort(h1));
                *(ushort2*)(g_phiql + ro1 + n0) = make_ushort2(__bfloat16_as_ushort(l0), __bfloat16_as_ushort(l1));
                v0 = expf(acc[i][j][2] - mx2) * 0.0625f + 1e-6f;
                v1 = expf(acc[i][j][3] - mx2) * 0.0625f + 1e-6f;
                bsplit(v0, h0, l0); bsplit(v1, h1, l1);
                *(ushort2*)(g_phiqh + ro2 + n0) = make_ushort2(__bfloat16_as_ushort(h0), __bfloat16_as_ushort(h1));
                *(ushort2*)(g_phiql + ro2 + n0) = make_ushort2(__bfloat16_as_ushort(l0), __bfloat16_as_ushort(l1));
            }
        }
    } else {
        float bm = -1e30f;
#pragma unroll
        for (int i = 0; i < 2; i++) {
            int r1 = wm * 32 + i * 16 + (lane >> 2);
            size_t ro1 = (row0 + r1) * 256, ro2 = (row0 + r1 + 8) * 256;
#pragma unroll
            for (int j = 0; j < 8; j++) {
                int n0 = (j >> 2) * 128 + wn * 32 + (j & 3) * 8 + (lane & 3) * 2;
                *(float2*)(g_phik + ro1 + n0) = make_float2(acc[i][j][0], acc[i][j][1]);
                *(float2*)(g_phik + ro2 + n0) = make_float2(acc[i][j][2], acc[i][j][3]);
                bm = fmaxf(bm, fmaxf(fmaxf(acc[i][j][0], acc[i][j][1]),
                                     fmaxf(acc[i][j][2], acc[i][j][3])));
            }
        }
#pragma unroll
        for (int o = 16; o > 0; o >>= 1)
            bm = fmaxf(bm, __shfl_xor_sync(0xffffffffu, bm, o));
        if (lane == 0) rowred[wid] = bm;
        __syncthreads();
        if (t == 0) {
            float m = rowred[0];
            for (int w = 1; w < 8; w++) m = fmaxf(m, rowred[w]);
            g_part[bid - 2048] = m;
        }
    }
}

__global__ void reduce_max_kernel(const float* __restrict__ partials, int n)
{
    __shared__ float red[256];
    int t = threadIdx.x;
    float mx = -1e30f;
    for (int i = t; i < n; i += 256) mx = fmaxf(mx, partials[i]);
    red[t] = mx; __syncthreads();
    for (int o = 128; o > 0; o >>= 1) {
        if (t < o) red[t] = fmaxf(red[t], red[t + o]);
        __syncthreads();
    }
    if (t == 0) g_zmax = red[0];
}

__global__ void expk_ksum_kernel()
{
    int c = blockIdx.x, bh = blockIdx.y, t = threadIdx.x;
    size_t base = ((size_t)bh * Ss + (size_t)c * 128) * 256;
    float zm = g_zmax;
    float sum = 0.f;
    for (int j = 0; j < 128; j++) {
        size_t off = base + (size_t)j * 256 + t;
        float v = expf(g_phik[off] - zm) * 0.0625f + 1e-6f;
        g_phik[off] = v;
        __nv_bfloat16 h, l;
        bsplit(v, h, l);
        g_phikh[off] = h; g_phikl[off] = l;
        sum += v;
    }
    g_ksum[((size_t)bh * NCn + c) * 256 + t] = sum;
}

// ---------------- per-chunk KV = phi_k^T @ v, transposed [d,m] output ---------
__global__ void kvchunk_kernel()
{
    __shared__ float pks[32 * 256];
    __shared__ float vs[32 * 64];
    int dh = blockIdx.x;
    int c  = blockIdx.y;
    int bh = blockIdx.z;
    int t = threadIdx.x, tx = t & 15, ty = t >> 4;
    const float* pk = g_phik + ((size_t)bh * Ss + (size_t)c * 128) * 256;
    const float* vv = g_v    + ((size_t)bh * Ss + (size_t)c * 128) * 128 + dh * 64;
    float acc[16][4];
#pragma unroll
    for (int a = 0; a < 16; a++)
#pragma unroll
        for (int b2 = 0; b2 < 4; b2++) acc[a][b2] = 0.f;

    for (int j0 = 0; j0 < 128; j0 += 32) {
        __syncthreads();
        for (int i = t; i < 32 * 256; i += 256) pks[i] = pk[(size_t)j0 * 256 + i];
        for (int i = t; i < 32 * 64; i += 256) {
            int j = i >> 6, d = i & 63;
            vs[i] = vv[(size_t)(j0 + j) * 128 + d];
        }
        __syncthreads();
        for (int j = 0; j < 32; j++) {
            float a[16], b4[4];
#pragma unroll
            for (int mi = 0; mi < 16; mi++) a[mi] = pks[j * 256 + tx + 16 * mi];
#pragma unroll
            for (int di = 0; di < 4; di++) b4[di] = vs[j * 64 + ty * 4 + di];
#pragma unroll
            for (int mi = 0; mi < 16; mi++)
#pragma unroll
                for (int di = 0; di < 4; di++)
                    acc[mi][di] = fmaf(a[mi], b4[di], acc[mi][di]);
        }
    }
    float* outp = g_kv + ((size_t)bh * NCn + c) * 32768 + (size_t)dh * 64 * 256;
#pragma unroll
    for (int di = 0; di < 4; di++) {
        int d = ty * 4 + di;
#pragma unroll
        for (int mi = 0; mi < 16; mi++)
            outp[(size_t)d * 256 + tx + 16 * mi] = acc[mi][di];
    }
}

__global__ void kvprefix_kernel()
{
    int e = blockIdx.x * 256 + threadIdx.x;
    int bh = blockIdx.y;
    size_t base = (size_t)bh * NCn * 32768 + e;
    float run = 0.f;
    for (int c = 0; c < NCn; c++) {
        size_t p = base + (size_t)c * 32768;
        float v = g_kv[p];
        __nv_bfloat16 h, l; bsplit(run, h, l);
        g_kvth[p] = h; g_kvtl[p] = l;
        run += v;
    }
}

__global__ void ksumprefix_kernel()
{
    int bh = blockIdx.x, m = threadIdx.x;
    float run = 0.f;
    for (int c = 0; c < NCn; c++) {
        size_t p = ((size_t)bh * NCn + c) * 256 + m;
        float v = g_ksum[p];
        g_ksum[p] = run;
        run += v;
    }
}

// ---------------- attention main: 64 q-rows/CTA, 2 CTAs/SM --------------------
// smem: STAGE @0 (69632)  [A/C: QH@0 9216, QL@9216, KH@18432 18432, KL@36864]
//                         [B:   VH@0 34816, VL@34816]
// PH @69632 (17408), PL @87040 (17408)
// den_part @104448 (1024), den2 @105472 (256), den_s @105728 (256), ksum @105984 (1024)
#define ATTN_SMEM 107520
__global__ void __launch_bounds__(256, 2) attn_kernel()
{
    extern __shared__ char smem[];
    const uint32_t sb = smem_u32(smem);
    const int t = threadIdx.x, lane = t & 31, wid = t >> 5;
    const int wm = wid >> 2, wn = wid & 3;
    const int c = blockIdx.x >> 1, mh = blockIdx.x & 1;
    const int h = blockIdx.y, b = blockIdx.z;
    const int kvh = h >> 1, bh = b * HKVn + kvh;
    const size_t qoff = (((size_t)(b * Hh + h)) * Ss + (size_t)c * 128 + mh * 64) * 256;
    const size_t koff = ((size_t)bh * Ss + (size_t)c * 128) * 256;

    float* den_part = (float*)(smem + 104448);
    float* den2_arr = (float*)(smem + 105472);
    float* den_s    = (float*)(smem + 105728);
    float* ksum_s   = (float*)(smem + 105984);

    ksum_s[t] = g_ksum[((size_t)bh * NCn + c) * 256 + t];

    const int arow = wm * 32 + (lane & 15);
    const int acolB = (lane >> 4) * 16;
    const int brow = wn * 32 + (lane & 7) + ((lane >> 4) & 1) * 8;
    const int bcolB = ((lane >> 3) & 1) * 16;

    // ---- phase A: P = phi_q(64 rows) @ phi_k^T(128) ; k = 256 in chunks of 64
    const __nv_bfloat16* qsrc[2] = { g_phiqh + qoff, g_phiql + qoff };
    const __nv_bfloat16* ksrc[2] = { g_phikh + koff, g_phikl + koff };
    auto issueA = [&](int kc) {
#pragma unroll
        for (int idx = t; idx < 3072; idx += 256) {
            uint32_t dst; const __nv_bfloat16* src;
            if (idx < 1024) {
                int tile = idx >> 9, rem = idx & 511;
                int r = rem >> 3, v = rem & 7;
                dst = sb + tile * 9216 + r * 144 + v * 16;
                src = qsrc[tile] + (size_t)r * 256 + kc * 64 + v * 8;
            } else {
                int x = idx - 1024;
                int tile = x >> 10, rem = x & 1023;
                int r = rem >> 3, v = rem & 7;
                dst = sb + 18432 + tile * 18432 + r * 144 + v * 16;
                src = ksrc[tile] + (size_t)r * 256 + kc * 64 + v * 8;
            }
            cp16(dst, src);
        }
        cp_commit();
    };

    float accP[2][4][4];
#pragma unroll
    for (int i = 0; i < 2; i++)
#pragma unroll
        for (int j = 0; j < 4; j++)
#pragma unroll
            for (int k = 0; k < 4; k++) accP[i][j][k] = 0.f;

    for (int kc = 0; kc < 4; kc++) {
        issueA(kc);
        cp_wait0();
        __syncthreads();
#pragma unroll
        for (int ks = 0; ks < 4; ks++) {
            int kb = ks * 32;
            uint32_t qh[2][4], ql[2][4], bhf[4][2], blf[4][2];
#pragma unroll
            for (int i = 0; i < 2; i++) {
                uint32_t off = (uint32_t)(arow + i * 16) * 144 + kb + acolB;
                ldmx4(qh[i], sb + off);
                ldmx4(ql[i], sb + 9216 + off);
            }
#pragma unroll
            for (int nt = 0; nt < 2; nt++) {
                uint32_t off = (uint32_t)(brow + nt * 16) * 144 + kb + bcolB;
                uint32_t rh[4], rl[4];
                ldmx4(rh, sb + 18432 + off);
                ldmx4(rl, sb + 36864 + off);
                bhf[nt * 2][0] = rh[0]; bhf[nt * 2][1] = rh[1];
                bhf[nt * 2 + 1][0] = rh[2]; bhf[nt * 2 + 1][1] = rh[3];
                blf[nt * 2][0] = rl[0]; blf[nt * 2][1] = rl[1];
                blf[nt * 2 + 1][0] = rl[2]; blf[nt * 2 + 1][1] = rl[3];
            }
#pragma unroll
            for (int i = 0; i < 2; i++)
#pragma unroll
                for (int j = 0; j < 4; j++) {
                    mma16816(accP[i][j], qh[i], bhf[j]);
                    mma16816(accP[i][j], qh[i], blf[j]);
                    mma16816(accP[i][j], ql[i], bhf[j]);
                }
        }
        __syncthreads();
    }

    // ---- mask, split P (64x128) to smem, row sums ----
    __nv_bfloat16* Ph = (__nv_bfloat16*)(smem + 69632);
    __nv_bfloat16* Pl = (__nv_bfloat16*)(smem + 87040);
#pragma unroll
    for (int i = 0; i < 2; i++) {
        int r1 = wm * 32 + i * 16 + (lane >> 2);
        int rr = mh * 64 + r1;           // row within chunk (0..127)
        float rs1 = 0.f, rs2 = 0.f;
#pragma unroll
        for (int j = 0; j < 4; j++) {
            int n0 = wn * 32 + j * 8 + (lane & 3) * 2;
            float m00 = (n0     <= rr    ) ? accP[i][j][0] : 0.f;
            float m01 = (n0 + 1 <= rr    ) ? accP[i][j][1] : 0.f;
            float m10 = (n0     <= rr + 8) ? accP[i][j][2] : 0.f;
            float m11 = (n0 + 1 <= rr + 8) ? accP[i][j][3] : 0.f;
            rs1 += m00 + m01; rs2 += m10 + m11;
            __nv_bfloat16 hh, llv;
            bsplit(m00, hh, llv); Ph[r1 * 136 + n0] = hh;       Pl[r1 * 136 + n0] = llv;
            bsplit(m01, hh, llv); Ph[r1 * 136 + n0 + 1] = hh;   Pl[r1 * 136 + n0 + 1] = llv;
            bsplit(m10, hh, llv); Ph[(r1 + 8) * 136 + n0] = hh; Pl[(r1 + 8) * 136 + n0] = llv;
            bsplit(m11, hh, llv); Ph[(r1 + 8) * 136 + n0 + 1] = hh; Pl[(r1 + 8) * 136 + n0 + 1] = llv;
        }
        rs1 += __shfl_xor_sync(0xffffffffu, rs1, 1);
        rs1 += __shfl_xor_sync(0xffffffffu, rs1, 2);
        rs2 += __shfl_xor_sync(0xffffffffu, rs2, 1);
        rs2 += __shfl_xor_sync(0xffffffffu, rs2, 2);
        if ((lane & 3) == 0) {
            den_part[wn * 64 + r1] = rs1;
            den_part[wn * 64 + r1 + 8] = rs2;
        }
    }
    __syncthreads();
    if (t < 64)
        den_s[t] = den_part[t] + den_part[64 + t] + den_part[128 + t] + den_part[192 + t];

    // ---- phase B: O = P @ v ; v_t[d, s] tile 128x128, k = 128 ----
    const __nv_bfloat16* vtsrc[2] = {
        g_vth + (size_t)bh * 128 * 4096 + c * 128,
        g_vtl + (size_t)bh * 128 * 4096 + c * 128 };
#pragma unroll
    for (int idx = t; idx < 4096; idx += 256) {
        int tile = idx >> 11, rem = idx & 2047;
        int r = rem >> 4, v = rem & 15;
        cp16(sb + tile * 34816 + r * 272 + v * 16, vtsrc[tile] + (size_t)r * 4096 + v * 8);
    }
    cp_commit();
    cp_wait0();
    __syncthreads();

    float accO[2][4][4];
#pragma unroll
    for (int i = 0; i < 2; i++)
#pragma unroll
        for (int j = 0; j < 4; j++)
#pragma unroll
            for (int k = 0; k < 4; k++) accO[i][j][k] = 0.f;

#pragma unroll
    for (int ks = 0; ks < 8; ks++) {
        int kb = ks * 32;
        uint32_t ah_[2][4], al_[2][4], bhf[4][2], blf[4][2];
#pragma unroll
        for (int i = 0; i < 2; i++) {
            uint32_t off = (uint32_t)(arow + i * 16) * 272 + kb + acolB;
            ldmx4(ah_[i], sb + 69632 + off);
            ldmx4(al_[i], sb + 87040 + off);
        }
#pragma unroll
        for (int nt = 0; nt < 2; nt++) {
            uint32_t off = (uint32_t)(brow + nt * 16) * 272 + kb + bcolB;
            uint32_t rh[4], rl[4];
            ldmx4(rh, sb + off);
            ldmx4(rl, sb + 34816 + off);
            bhf[nt * 2][0] = rh[0]; bhf[nt * 2][1] = rh[1];
            bhf[nt * 2 + 1][0] = rh[2]; bhf[nt * 2 + 1][1] = rh[3];
            blf[nt * 2][0] = rl[0]; blf[nt * 2][1] = rl[1];
            blf[nt * 2 + 1][0] = rl[2]; blf[nt * 2 + 1][1] = rl[3];
        }
#pragma unroll
        for (int i = 0; i < 2; i++)
#pragma unroll
            for (int j = 0; j < 4; j++) {
                mma16816(accO[i][j], ah_[i], bhf[j]);
                mma16816(accO[i][j], ah_[i], blf[j]);
                mma16816(accO[i][j], al_[i], bhf[j]);
            }
    }
    __syncthreads();

    // ---- phase C: O += phi_q @ KV_pre ; kv_t[d, m], k = 256 in chunks of 64 --
    const __nv_bfloat16* kvsrc[2] = {
        g_kvth + ((size_t)bh * NCn + c) * 32768,
        g_kvtl + ((size_t)bh * NCn + c) * 32768 };
    auto issueC = [&](int kc) {
#pragma unroll
        for (int idx = t; idx < 3072; idx += 256) {
            uint32_t dst; const __nv_bfloat16* src;
            if (idx < 1024) {
                int tile = idx >> 9, rem = idx & 511;
                int r = rem >> 3, v = rem & 7;
                dst = sb + tile * 9216 + r * 144 + v * 16;
                src = qsrc[tile] + (size_t)r * 256 + kc * 64 + v * 8;
            } else {
                int x = idx - 1024;
                int tile = x >> 10, rem = x & 1023;
                int r = rem >> 3, v = rem & 7;
                dst = sb + 18432 + tile * 18432 + r * 144 + v * 16;
                src = kvsrc[tile] + (size_t)r * 256 + kc * 64 + v * 8;
            }
            cp16(dst, src);
        }
        cp_commit();
    };

    float den2r = 0.f;
    for (int kc = 0; kc < 4; kc++) {
        issueC(kc);
        cp_wait0();
        __syncthreads();
#pragma unroll
        for (int ks = 0; ks < 4; ks++) {
            int kb = ks * 32;
            uint32_t qh[2][4], ql[2][4], bhf[4][2], blf[4][2];
#pragma unroll
            for (int i = 0; i < 2; i++) {
                uint32_t off = (uint32_t)(arow + i * 16) * 144 + kb + acolB;
                ldmx4(qh[i], sb + off);
                ldmx4(ql[i], sb + 9216 + off);
            }
#pragma unroll
            for (int nt = 0; nt < 2; nt++) {
                uint32_t off = (uint32_t)(brow + nt * 16) * 144 + kb + bcolB;
                uint32_t rh[4], rl[4];
                ldmx4(rh, sb + 18432 + off);
                ldmx4(rl, sb + 36864 + off);
                bhf[nt * 2][0] = rh[0]; bhf[nt * 2][1] = rh[1];
                bhf[nt * 2 + 1][0] = rh[2]; bhf[nt * 2 + 1][1] = rh[3];
                blf[nt * 2][0] = rl[0]; blf[nt * 2][1] = rl[1];
                blf[nt * 2 + 1][0] = rl[2]; blf[nt * 2 + 1][1] = rl[3];
            }
#pragma unroll
            for (int i = 0; i < 2; i++)
#pragma unroll
                for (int j = 0; j < 4; j++) {
                    mma16816(accO[i][j], qh[i], bhf[j]);
                    mma16816(accO[i][j], qh[i], blf[j]);
                    mma16816(accO[i][j], ql[i], bhf[j]);
                }
        }
        if (t < 64) {
            const __nv_bfloat16* qh_e = (const __nv_bfloat16*)(smem);
            const __nv_bfloat16* ql_e = (const __nv_bfloat16*)(smem + 9216);
            for (int mm = 0; mm < 64; mm++)
                den2r += (__bfloat162float(qh_e[t * 72 + mm]) +
                          __bfloat162float(ql_e[t * 72 + mm])) * ksum_s[kc * 64 + mm];
        }
        __syncthreads();
    }
    if (t < 64) den2_arr[t] = den2r;
    __syncthreads();

    // ---- epilogue ----
#pragma unroll
    for (int i = 0; i < 2; i++) {
        int r1 = wm * 32 + i * 16 + (lane >> 2);
        float dn1 = den_s[r1] + den2_arr[r1] + 1e-6f;
        float dn2 = den_s[r1 + 8] + den2_arr[r1 + 8] + 1e-6f;
        int s1 = c * 128 + mh * 64 + r1;
#pragma unroll
        for (int j = 0; j < 4; j++) {
            int n0 = wn * 32 + j * 8 + (lane & 3) * 2;
            float v00 = accO[i][j][0] / dn1, v01 = accO[i][j][1] / dn1;
            float v10 = accO[i][j][2] / dn2, v11 = accO[i][j][3] / dn2;
            size_t o1 = ((size_t)b * Ss + s1) * 2048 + h * 128 + n0;
            size_t o2 = ((size_t)b * Ss + s1 + 8) * 2048 + h * 128 + n0;
            __nv_bfloat16 hh, llv;
            bsplit(v00, hh, llv); g_ah[o1] = hh;     g_al[o1] = llv;
            bsplit(v01, hh, llv); g_ah[o1 + 1] = hh; g_al[o1 + 1] = llv;
            bsplit(v10, hh, llv); g_ah[o2] = hh;     g_al[o2] = llv;
            bsplit(v11, hh, llv); g_ah[o2 + 1] = hh; g_al[o2 + 1] = llv;
        }
    }
}

// ---------------- launch ------------------------------------------------------
extern "C" void kernel_launch(void* const* d_in, const int* in_sizes, int n_in,
                              void* d_out, int out_size)
{
    const float* hs   = (const float*)d_in[0];
    const float* cosp = (const float*)d_in[1];
    const float* sinp = (const float*)d_in[2];
    const float* wq   = (const float*)d_in[3];
    const float* wk   = (const float*)d_in[4];
    const float* wv   = (const float*)d_in[5];
    const float* wo   = (const float*)d_in[6];
    const float* proj = (const float*)d_in[7];
    float* out = (float*)d_out;

    float *ppart;
    cudaGetSymbolAddress((void**)&ppart, g_part);
    __nv_bfloat16 *ah, *al, *wqh, *wql, *wkh, *wkl, *wvh, *wvl, *woh, *wol;
    __nv_bfloat16 *projh, *projl;
    cudaGetSymbolAddress((void**)&ah,  g_ah);
    cudaGetSymbolAddress((void**)&al,  g_al);
    cudaGetSymbolAddress((void**)&wqh, g_wqh);
    cudaGetSymbolAddress((void**)&wql, g_wql);
    cudaGetSymbolAddress((void**)&wkh, g_wkh);
    cudaGetSymbolAddress((void**)&wkl, g_wkl);
    cudaGetSymbolAddress((void**)&wvh, g_wvh);
    cudaGetSymbolAddress((void**)&wvl, g_wvl);
    cudaGetSymbolAddress((void**)&woh, g_woh);
    cudaGetSymbolAddress((void**)&wol, g_wol);
    cudaGetSymbolAddress((void**)&projh, g_projh);
    cudaGetSymbolAddress((void**)&projl, g_projl);

    cudaFuncSetAttribute(featmap_hmma, cudaFuncAttributeMaxDynamicSharedMemorySize, FM_SMEM);
    cudaFuncSetAttribute(attn_kernel,  cudaFuncAttributeMaxDynamicSharedMemorySize, ATTN_SMEM);
    cudaFuncSetAttribute(hmma_gemm,    cudaFuncAttributeMaxDynamicSharedMemorySize, 2 * STG_BYTES);
    cudaFuncSetAttribute(hmma_qkv,     cudaFuncAttributeMaxDynamicSharedMemorySize, 2 * STG_BYTES);

    // splits
    split_kernel<<<16384, 256>>>(hs, ah, al, 4194304);
    split_kernel<<<4096,  256>>>(wq, wqh, wql, 1048576);
    split_kernel<<<2048,  256>>>(wk, wkh, wkl, 524288);
    split_kernel<<<2048,  256>>>(wv, wvh, wvl, 524288);
    split_kernel<<<4096,  256>>>(wo, woh, wol, 1048576);
    split_kernel<<<32,    256>>>(proj, projh, projl, 8192);

    // fused QKV projection (R10 config; V blocks also emit vth/vtl)
    hmma_qkv<<<dim3(32, 64), 256, 2 * STG_BYTES>>>();

    // feature maps (q + k merged; 2-pass proj, 2 CTAs/SM)
    featmap_hmma<<<3072, 256, FM_SMEM>>>(cosp, sinp);
    reduce_max_kernel<<<1, 256>>>(ppart, 1024);
    expk_ksum_kernel<<<dim3(NCn, Bb * HKVn), 256>>>();

    // chunk states
    kvchunk_kernel<<<dim3(2, NCn, Bb * HKVn), 256>>>();
    kvprefix_kernel<<<dim3(128, Bb * HKVn), 256>>>();
    ksumprefix_kernel<<<Bb * HKVn, 256>>>();

    // attention (64 q-rows/CTA, 2 CTAs/SM)
    attn_kernel<<<dim3(NCn * 2, Hh, Bb), 256, ATTN_SMEM>>>();

    // output projection (R10 config)
    hmma_gemm<<<dim3(16, 64), 256, 2 * STG_BYTES>>>(ah, al, woh, wol, out, 2048, 0, 0);
}

// round 16
// speedup vs baseline: 1.0062x; 1.0062x over previous
#include <cuda_runtime.h>
#include <cuda_bf16.h>
#include <cstdint>

#define Bb 2
#define Ss 4096
#define HIDN 2048
#define Hh 16
#define HKVn 8
#define Dd 128
#define Mm 256
#define NCn 32

// ---------------- scratch -----------------------------------------------------
__device__ float g_q[(size_t)Bb * Hh * Ss * Dd];
__device__ float g_k[(size_t)Bb * HKVn * Ss * Dd];
__device__ float g_v[(size_t)Bb * HKVn * Ss * Dd];
__device__ float g_phik[(size_t)Bb * HKVn * Ss * Mm];
__device__ float g_kv[(size_t)Bb * HKVn * NCn * Mm * Dd];   // [bh, c, d, m]
__device__ float g_ksum[(size_t)Bb * HKVn * NCn * Mm];
__device__ float g_part[4096];

// bf16 hi/lo operands
__device__ __nv_bfloat16 g_ah[16777216], g_al[16777216];
__device__ __nv_bfloat16 g_wqh[4194304], g_wql[4194304];
__device__ __nv_bfloat16 g_wkh[2097152], g_wkl[2097152];
__device__ __nv_bfloat16 g_wvh[2097152], g_wvl[2097152];
__device__ __nv_bfloat16 g_woh[4194304], g_wol[4194304];
__device__ __nv_bfloat16 g_projh[32768], g_projl[32768];
__device__ __nv_bfloat16 g_phiqh[33554432], g_phiql[33554432];
__device__ __nv_bfloat16 g_phikh[16777216], g_phikl[16777216];
__device__ __nv_bfloat16 g_vth[8388608],  g_vtl[8388608];      // [bh, d, s]
__device__ __nv_bfloat16 g_kvth[16777216], g_kvtl[16777216];   // [bh, c, d, m]

// ---------------- helpers -----------------------------------------------------
__device__ __forceinline__ uint32_t smem_u32(const void* p) {
    uint32_t a;
    asm("{ .reg .u64 t; cvta.to.shared.u64 t, %1; cvt.u32.u64 %0, t; }" : "=r"(a) : "l"(p));
    return a;
}
__device__ __forceinline__ void cp16(uint32_t dst, const void* src) {
    asm volatile("cp.async.cg.shared.global [%0], [%1], 16;" :: "r"(dst), "l"(src));
}
__device__ __forceinline__ void cp_commit() { asm volatile("cp.async.commit_group;"); }
__device__ __forceinline__ void cp_wait1()  { asm volatile("cp.async.wait_group 1;"); }
__device__ __forceinline__ void cp_wait0()  { asm volatile("cp.async.wait_group 0;"); }

__device__ __forceinline__ void ldmx4(uint32_t* r, uint32_t addr) {
    asm volatile("ldmatrix.sync.aligned.m8n8.x4.shared.b16 {%0,%1,%2,%3}, [%4];"
                 : "=r"(r[0]), "=r"(r[1]), "=r"(r[2]), "=r"(r[3]) : "r"(addr));
}
__device__ __forceinline__ void mma16816(float* c, const uint32_t* a, const uint32_t* b) {
    asm volatile(
        "mma.sync.aligned.m16n8k16.row.col.f32.bf16.bf16.f32 "
        "{%0,%1,%2,%3},{%4,%5,%6,%7},{%8,%9},{%0,%1,%2,%3};"
        : "+f"(c[0]), "+f"(c[1]), "+f"(c[2]), "+f"(c[3])
        : "r"(a[0]), "r"(a[1]), "r"(a[2]), "r"(a[3]), "r"(b[0]), "r"(b[1]));
}
__device__ __forceinline__ void bsplit(float v, __nv_bfloat16& h, __nv_bfloat16& l) {
    h = __float2bfloat16(v);
    l = __float2bfloat16(v - __bfloat162float(h));
}

// ---------------- fp32 -> bf16 hi/lo split -----------------------------------
__global__ void split_kernel(const float* __restrict__ x, __nv_bfloat16* __restrict__ hi,
                             __nv_bfloat16* __restrict__ lo, int n4)
{
    int i = blockIdx.x * 256 + threadIdx.x;
    if (i < n4) {
        float4 v = ((const float4*)x)[i];
        __nv_bfloat16 h0, h1, h2, h3, l0, l1, l2, l3;
        bsplit(v.x, h0, l0); bsplit(v.y, h1, l1);
        bsplit(v.z, h2, l2); bsplit(v.w, h3, l3);
        ushort4 hh, ll;
        hh.x = __bfloat16_as_ushort(h0); hh.y = __bfloat16_as_ushort(h1);
        hh.z = __bfloat16_as_ushort(h2); hh.w = __bfloat16_as_ushort(h3);
        ll.x = __bfloat16_as_ushort(l0); ll.y = __bfloat16_as_ushort(l1);
        ll.z = __bfloat16_as_ushort(l2); ll.w = __bfloat16_as_ushort(l3);
        ((ushort4*)hi)[i] = hh;
        ((ushort4*)lo)[i] = ll;
    }
}

// ---------------- HMMA bf16x3 GEMM body, CTA tile 128x128 (R10 proven) --------
#define STG_BYTES 40960
#define TILE_BYTES 10240
__device__ __forceinline__ void gemm_body(
    char* smem,
    const __nv_bfloat16* Ah, const __nv_bfloat16* Al,
    const __nv_bfloat16* Wh, const __nv_bfloat16* Wl,
    float* C, int N, int mode, int NH, int row0, int col0, int vtrans)
{
    const uint32_t sb = smem_u32(smem);
    const int t = threadIdx.x, lane = t & 31, wid = t >> 5;
    const int wm = wid >> 2, wn = wid & 3;

    const __nv_bfloat16* gA[2] = { Ah + (size_t)row0 * 2048, Al + (size_t)row0 * 2048 };
    const __nv_bfloat16* gB[2] = { Wh + (size_t)col0 * 2048, Wl + (size_t)col0 * 2048 };

    auto issue = [&](int s, int kc) {
        uint32_t base = sb + s * STG_BYTES;
#pragma unroll
        for (int idx = t; idx < 2048; idx += 256) {
            int tile = idx >> 9;
            int rem = idx & 511;
            int r = rem >> 2, c = rem & 3;
            const __nv_bfloat16* src =
                (tile < 2 ? gA[tile] : gB[tile - 2]) + (size_t)r * 2048 + kc * 32 + c * 8;
            cp16(base + tile * TILE_BYTES + r * 80 + c * 16, src);
        }
        cp_commit();
    };

    float acc[4][4][4];
#pragma unroll
    for (int i = 0; i < 4; i++)
#pragma unroll
        for (int j = 0; j < 4; j++)
#pragma unroll
            for (int k = 0; k < 4; k++) acc[i][j][k] = 0.f;

    issue(0, 0);
    issue(1, 1);

    const int arow = wm * 64 + (lane & 15);
    const int acol = (lane >> 4) * 16;
    const int brow = wn * 32 + (lane & 7) + ((lane >> 4) & 1) * 8;
    const int bcol = ((lane >> 3) & 1) * 16;

    for (int kc = 0; kc < 64; kc++) {
        cp_wait1();
        __syncthreads();
        uint32_t base = sb + (kc & 1) * STG_BYTES;
        uint32_t aH = base, aL = base + TILE_BYTES;
        uint32_t bH = base + 2 * TILE_BYTES, bL = base + 3 * TILE_BYTES;
#pragma unroll
        for (int ks = 0; ks < 2; ks++) {
            uint32_t kb = ks * 32;
            uint32_t ah[4][4], al[4][4], bh[4][2], bl[4][2];
#pragma unroll
            for (int i = 0; i < 4; i++) {
                uint32_t off = (uint32_t)(arow + i * 16) * 80 + kb + acol;
                ldmx4(ah[i], aH + off);
                ldmx4(al[i], aL + off);
            }
#pragma unroll
            for (int nt = 0; nt < 2; nt++) {
                uint32_t off = (uint32_t)(brow + nt * 16) * 80 + kb + bcol;
                uint32_t rh[4], rl[4];
                ldmx4(rh, bH + off);
                ldmx4(rl, bL + off);
                bh[nt * 2][0] = rh[0]; bh[nt * 2][1] = rh[1];
                bh[nt * 2 + 1][0] = rh[2]; bh[nt * 2 + 1][1] = rh[3];
                bl[nt * 2][0] = rl[0]; bl[nt * 2][1] = rl[1];
                bl[nt * 2 + 1][0] = rl[2]; bl[nt * 2 + 1][1] = rl[3];
            }
#pragma unroll
            for (int i = 0; i < 4; i++)
#pragma unroll
                for (int j = 0; j < 4; j++) {
                    mma16816(acc[i][j], ah[i], bh[j]);
                    mma16816(acc[i][j], ah[i], bl[j]);
                    mma16816(acc[i][j], al[i], bh[j]);
                }
        }
        __syncthreads();
        if (kc + 2 < 64) issue(kc & 1, kc + 2);
        else cp_commit();
    }

#pragma unroll
    for (int i = 0; i < 4; i++) {
        int m = wm * 64 + i * 16 + (lane >> 2);
#pragma unroll
        for (int j = 0; j < 4; j++) {
            int n = wn * 32 + j * 8 + (lane & 3) * 2;
#pragma unroll
            for (int half = 0; half < 2; half++) {
                int mr = m + half * 8;
                float2 v;
                v.x = acc[i][j][half * 2 + 0];
                v.y = acc[i][j][half * 2 + 1];
                if (mode == 0) {
                    *(float2*)(C + (size_t)(row0 + mr) * N + col0 + n) = v;
                } else {
                    int b = (row0 + mr) >> 12, srow = (row0 + mr) & 4095;
                    int h = col0 >> 7;
                    *(float2*)(C + ((((size_t)b * NH + h) * 4096 + srow) << 7) + n) = v;
                }
            }
        }
    }

    if (vtrans) {
        __syncthreads();
        float* Ts = (float*)smem;
#pragma unroll
        for (int i = 0; i < 4; i++) {
            int m = wm * 64 + i * 16 + (lane >> 2);
#pragma unroll
            for (int j = 0; j < 4; j++) {
                int n = wn * 32 + j * 8 + (lane & 3) * 2;
#pragma unroll
                for (int half = 0; half < 2; half++) {
                    int mr = m + half * 8;
                    Ts[mr * 133 + n]     = acc[i][j][half * 2 + 0];
                    Ts[mr * 133 + n + 1] = acc[i][j][half * 2 + 1];
                }
            }
        }
        __syncthreads();
        int b = row0 >> 12, s0 = row0 & 4095;
        int kvh = col0 >> 7;
        size_t vbase = ((size_t)(b * HKVn + kvh)) * 128 * 4096;
        for (int idx = t; idx < 16384; idx += 256) {
            int d = idx >> 7, ss = idx & 127;
            float val = Ts[ss * 133 + d];
            __nv_bfloat16 h, l; bsplit(val, h, l);
            size_t o = vbase + (size_t)d * 4096 + s0 + ss;
            g_vth[o] = h; g_vtl[o] = l;
        }
    }
}

// O projection kernel
__global__ void __launch_bounds__(256, 2)
hmma_gemm(const __nv_bfloat16* __restrict__ Ah, const __nv_bfloat16* __restrict__ Al,
          const __nv_bfloat16* __restrict__ Wh, const __nv_bfloat16* __restrict__ Wl,
          float* __restrict__ C, int N, int mode, int NH)
{
    extern __shared__ char smem[];
    gemm_body(smem, Ah, Al, Wh, Wl, C, N, mode, NH, blockIdx.y * 128, blockIdx.x * 128, 0);
}

// fused QKV projection
__global__ void __launch_bounds__(256, 2)
hmma_qkv()
{
    extern __shared__ char smem[];
    int bx = blockIdx.x;
    const __nv_bfloat16 *Wh, *Wl;
    float* C;
    int NH, col0, vtrans;
    if (bx < 16)      { Wh = g_wqh; Wl = g_wql; C = g_q; NH = 16; col0 = bx * 128; vtrans = 0; }
    else if (bx < 24) { Wh = g_wkh; Wl = g_wkl; C = g_k; NH = 8;  col0 = (bx - 16) * 128; vtrans = 0; }
    else              { Wh = g_wvh; Wl = g_wvl; C = g_v; NH = 8;  col0 = (bx - 24) * 128; vtrans = 1; }
    gemm_body(smem, g_ah, g_al, Wh, Wl, C, 0, 1, NH, blockIdx.y * 128, col0, vtrans);
}

// ---------------- feature map: HMMA, rope fused, q+k merged, 2 proj passes ----
#define FM_SMEM 106496
#define FMP 272
__global__ void __launch_bounds__(256, 2)
featmap_hmma(const float* __restrict__ cosp, const float* __restrict__ sinp)
{
    extern __shared__ char smem[];
    const uint32_t sb = smem_u32(smem);
    const int t = threadIdx.x, lane = t & 31, wid = t >> 5;
    const int wm = wid >> 2, wn = wid & 3;
    const int bid = blockIdx.x;
    const int isq = (bid < 2048);
    const float* X = isq ? g_q : g_k;
    const int NH = isq ? 16 : 8;
    const size_t row0 = (size_t)(isq ? bid : bid - 2048) * 64;

    ushort* XH = (ushort*)(smem);
    ushort* XL = (ushort*)(smem + 17408);
    float* maxpart = (float*)(smem + 104448);
    float* rowred  = (float*)(smem + 105472);
    float* sq      = (float*)(smem + 105728);

    auto issueP = [&](int p) {
#pragma unroll
        for (int idx = t; idx < 4096; idx += 256) {
            int tile = idx >> 11, rem = idx & 2047;
            int r = rem >> 4, v = rem & 15;
            const __nv_bfloat16* src = (tile ? g_projl : g_projh) + (p * 128 + r) * 128 + v * 8;
            cp16(sb + 34816 + tile * 34816 + r * FMP + v * 16, src);
        }
        cp_commit();
    };
    issueP(0);

    const float sc = 0.29730177875068026f;
    for (int i = t; i < 64 * 64; i += 256) {
        int r = i >> 6, d = i & 63;
        size_t row = row0 + r;
        int b = (int)(row / ((size_t)NH * 4096));
        int s = (int)(row & 4095);
        size_t base = row * 128;
        float x1 = X[base + d], x2 = X[base + d + 64];
        size_t cb = (((size_t)b * 4096 + s) << 7);
        float c1 = cosp[cb + d],      s1v = sinp[cb + d];
        float c2 = cosp[cb + d + 64], s2v = sinp[cb + d + 64];
        float y1 = (x1 * c1 - x2 * s1v) * sc;
        float y2 = (x2 * c2 + x1 * s2v) * sc;
        __nv_bfloat16 h, l;
        bsplit(y1, h, l);
        XH[r * 136 + d] = __bfloat16_as_ushort(h);
        XL[r * 136 + d] = __bfloat16_as_ushort(l);
        bsplit(y2, h, l);
        XH[r * 136 + d + 64] = __bfloat16_as_ushort(h);
        XL[r * 136 + d + 64] = __bfloat16_as_ushort(l);
    }
    __syncthreads();

    {
        int r = t >> 2, qq = t & 3;
        float p = 0.f;
        for (int dd = 0; dd < 32; dd++) {
            int d = qq * 32 + dd;
            float v = __bfloat162float(__ushort_as_bfloat16(XH[r * 136 + d])) +
                      __bfloat162float(__ushort_as_bfloat16(XL[r * 136 + d]));
            p = fmaf(v, v, p);
        }
        p += __shfl_xor_sync(0xffffffffu, p, 1);
        p += __shfl_xor_sync(0xffffffffu, p, 2);
        if (qq == 0) sq[r] = 0.5f * p;
    }

    float acc[2][8][4];
#pragma unroll
    for (int i = 0; i < 2; i++)
#pragma unroll
        for (int j = 0; j < 8; j++)
#pragma unroll
            for (int k = 0; k < 4; k++) acc[i][j][k] = 0.f;

    const int arow = wm * 32 + (lane & 15);
    const int acolB = (lane >> 4) * 16;
    const int brow = wn * 32 + (lane & 7) + ((lane >> 4) & 1) * 8;
    const int bcolB = ((lane >> 3) & 1) * 16;
    const uint32_t xh0 = sb, xl0 = sb + 17408;
    const uint32_t ph0 = sb + 34816, pl0 = sb + 69632;

#pragma unroll
    for (int p = 0; p < 2; p++) {
        cp_wait0();
        __syncthreads();
#pragma unroll
        for (int ks = 0; ks < 8; ks++) {
            uint32_t kb = ks * 32;
            uint32_t ah[2][4], al[2][4], bh[4][2], bl[4][2];
#pragma unroll
            for (int i = 0; i < 2; i++) {
                uint32_t off = (uint32_t)(arow + i * 16) * FMP + kb + acolB;
                ldmx4(ah[i], xh0 + off);
                ldmx4(al[i], xl0 + off);
            }
#pragma unroll
            for (int nt = 0; nt < 2; nt++) {
                uint32_t off = (uint32_t)(brow + nt * 16) * FMP + kb + bcolB;
                uint32_t rh[4], rl[4];
                ldmx4(rh, ph0 + off);
                ldmx4(rl, pl0 + off);
                bh[nt * 2][0] = rh[0]; bh[nt * 2][1] = rh[1];
                bh[nt * 2 + 1][0] = rh[2]; bh[nt * 2 + 1][1] = rh[3];
                bl[nt * 2][0] = rl[0]; bl[nt * 2][1] = rl[1];
                bl[nt * 2 + 1][0] = rl[2]; bl[nt * 2 + 1][1] = rl[3];
            }
#pragma unroll
            for (int i = 0; i < 2; i++)
#pragma unroll
                for (int jj = 0; jj < 4; jj++) {
                    mma16816(acc[i][p * 4 + jj], ah[i], bh[jj]);
                    mma16816(acc[i][p * 4 + jj], ah[i], bl[jj]);
                    mma16816(acc[i][p * 4 + jj], al[i], bh[jj]);
                }
        }
        if (p == 0) {
            __syncthreads();
            issueP(1);
        }
    }

#pragma unroll
    for (int i = 0; i < 2; i++) {
        int r1 = wm * 32 + i * 16 + (lane >> 2);
        float s1 = sq[r1], s2 = sq[r1 + 8];
#pragma unroll
        for (int j = 0; j < 8; j++) {
            acc[i][j][0] -= s1; acc[i][j][1] -= s1;
            acc[i][j][2] -= s2; acc[i][j][3] -= s2;
        }
    }

    if (isq) {
#pragma unroll
        for (int i = 0; i < 2; i++) {
            int r1 = wm * 32 + i * 16 + (lane >> 2);
            float m1 = -1e30f, m2 = -1e30f;
#pragma unroll
            for (int j = 0; j < 8; j++) {
                m1 = fmaxf(m1, fmaxf(acc[i][j][0], acc[i][j][1]));
                m2 = fmaxf(m2, fmaxf(acc[i][j][2], acc[i][j][3]));
            }
            m1 = fmaxf(m1, __shfl_xor_sync(0xffffffffu, m1, 1));
            m1 = fmaxf(m1, __shfl_xor_sync(0xffffffffu, m1, 2));
            m2 = fmaxf(m2, __shfl_xor_sync(0xffffffffu, m2, 1));
            m2 = fmaxf(m2, __shfl_xor_sync(0xffffffffu, m2, 2));
            if ((lane & 3) == 0) {
                maxpart[wn * 64 + r1] = m1;
                maxpart[wn * 64 + r1 + 8] = m2;
            }
        }
        __syncthreads();
        if (t < 64)
            rowred[t] = fmaxf(fmaxf(maxpart[t], maxpart[64 + t]),
                              fmaxf(maxpart[128 + t], maxpart[192 + t]));
        __syncthreads();
#pragma unroll
        for (int i = 0; i < 2; i++) {
            int r1 = wm * 32 + i * 16 + (lane >> 2);
            float mx1 = rowred[r1], mx2 = rowred[r1 + 8];
            size_t ro1 = (row0 + r1) * 256, ro2 = (row0 + r1 + 8) * 256;
#pragma unroll
            for (int j = 0; j < 8; j++) {
                int n0 = (j >> 2) * 128 + wn * 32 + (j & 3) * 8 + (lane & 3) * 2;
                __nv_bfloat16 h0, l0, h1, l1;
                float v0 = expf(acc[i][j][0] - mx1) * 0.0625f + 1e-6f;
                float v1 = expf(acc[i][j][1] - mx1) * 0.0625f + 1e-6f;
                bsplit(v0, h0, l0); bsplit(v1, h1, l1);
                *(ushort2*)(g_phiqh + ro1 + n0) = make_ushort2(__bfloat16_as_ushort(h0), __bfloat16_as_ushort(h1));
                *(ushort2*)(g_phiql + ro1 + n0) = make_ushort2(__bfloat16_as_ushort(l0), __bfloat16_as_ushort(l1));
                v0 = expf(acc[i][j][2] - mx2) * 0.0625f + 1e-6f;
                v1 = expf(acc[i][j][3] - mx2) * 0.0625f + 1e-6f;
                bsplit(v0, h0, l0); bsplit(v1, h1, l1);
                *(ushort2*)(g_phiqh + ro2 + n0) = make_ushort2(__bfloat16_as_ushort(h0), __bfloat16_as_ushort(h1));
                *(ushort2*)(g_phiql + ro2 + n0) = make_ushort2(__bfloat16_as_ushort(l0), __bfloat16_as_ushort(l1));
            }
        }
    } else {
        float bm = -1e30f;
#pragma unroll
        for (int i = 0; i < 2; i++) {
            int r1 = wm * 32 + i * 16 + (lane >> 2);
            size_t ro1 = (row0 + r1) * 256, ro2 = (row0 + r1 + 8) * 256;
#pragma unroll
            for (int j = 0; j < 8; j++) {
                int n0 = (j >> 2) * 128 + wn * 32 + (j & 3) * 8 + (lane & 3) * 2;
                *(float2*)(g_phik + ro1 + n0) = make_float2(acc[i][j][0], acc[i][j][1]);
                *(float2*)(g_phik + ro2 + n0) = make_float2(acc[i][j][2], acc[i][j][3]);
                bm = fmaxf(bm, fmaxf(fmaxf(acc[i][j][0], acc[i][j][1]),
                                     fmaxf(acc[i][j][2], acc[i][j][3])));
            }
        }
#pragma unroll
        for (int o = 16; o > 0; o >>= 1)
            bm = fmaxf(bm, __shfl_xor_sync(0xffffffffu, bm, o));
        if (lane == 0) rowred[wid] = bm;
        __syncthreads();
        if (t == 0) {
            float m = rowred[0];
            for (int w = 1; w < 8; w++) m = fmaxf(m, rowred[w]);
            g_part[bid - 2048] = m;
        }
    }
}

// fused: per-block global-max reduction + phi_k exp (fp32 + hi/lo) + chunk colsums
__global__ void expk_ksum_kernel()
{
    __shared__ float red[256];
    int c = blockIdx.x, bh = blockIdx.y, t = threadIdx.x;
    float mx = -1e30f;
    for (int i = t; i < 1024; i += 256) mx = fmaxf(mx, g_part[i]);
    red[t] = mx; __syncthreads();
    for (int o = 128; o > 0; o >>= 1) {
        if (t < o) red[t] = fmaxf(red[t], red[t + o]);
        __syncthreads();
    }
    float zm = red[0];

    size_t base = ((size_t)bh * Ss + (size_t)c * 128) * 256;
    float sum = 0.f;
    for (int j = 0; j < 128; j++) {
        size_t off = base + (size_t)j * 256 + t;
        float v = expf(g_phik[off] - zm) * 0.0625f + 1e-6f;
        g_phik[off] = v;
        __nv_bfloat16 h, l;
        bsplit(v, h, l);
        g_phikh[off] = h; g_phikl[off] = l;
        sum += v;
    }
    g_ksum[((size_t)bh * NCn + c) * 256 + t] = sum;
}

// ---------------- per-chunk KV = phi_k^T @ v, transposed [d,m] output ---------
__global__ void kvchunk_kernel()
{
    __shared__ float pks[32 * 256];
    __shared__ float vs[32 * 64];
    int dh = blockIdx.x;
    int c  = blockIdx.y;
    int bh = blockIdx.z;
    int t = threadIdx.x, tx = t & 15, ty = t >> 4;
    const float* pk = g_phik + ((size_t)bh * Ss + (size_t)c * 128) * 256;
    const float* vv = g_v    + ((size_t)bh * Ss + (size_t)c * 128) * 128 + dh * 64;
    float acc[16][4];
#pragma unroll
    for (int a = 0; a < 16; a++)
#pragma unroll
        for (int b2 = 0; b2 < 4; b2++) acc[a][b2] = 0.f;

    for (int j0 = 0; j0 < 128; j0 += 32) {
        __syncthreads();
        for (int i = t; i < 32 * 256; i += 256) pks[i] = pk[(size_t)j0 * 256 + i];
        for (int i = t; i < 32 * 64; i += 256) {
            int j = i >> 6, d = i & 63;
            vs[i] = vv[(size_t)(j0 + j) * 128 + d];
        }
        __syncthreads();
        for (int j = 0; j < 32; j++) {
            float a[16], b4[4];
#pragma unroll
            for (int mi = 0; mi < 16; mi++) a[mi] = pks[j * 256 + tx + 16 * mi];
#pragma unroll
            for (int di = 0; di < 4; di++) b4[di] = vs[j * 64 + ty * 4 + di];
#pragma unroll
            for (int mi = 0; mi < 16; mi++)
#pragma unroll
                for (int di = 0; di < 4; di++)
                    acc[mi][di] = fmaf(a[mi], b4[di], acc[mi][di]);
        }
    }
    float* outp = g_kv + ((size_t)bh * NCn + c) * 32768 + (size_t)dh * 64 * 256;
#pragma unroll
    for (int di = 0; di < 4; di++) {
        int d = ty * 4 + di;
#pragma unroll
        for (int mi = 0; mi < 16; mi++)
            outp[(size_t)d * 256 + tx + 16 * mi] = acc[mi][di];
    }
}

// exclusive prefix over chunks; writes bf16 hi/lo directly
__global__ void kvprefix_kernel()
{
    int e = blockIdx.x * 256 + threadIdx.x;
    int bh = blockIdx.y;
    size_t base = (size_t)bh * NCn * 32768 + e;
    float run = 0.f;
    for (int c = 0; c < NCn; c++) {
        size_t p = base + (size_t)c * 32768;
        float v = g_kv[p];
        __nv_bfloat16 h, l; bsplit(run, h, l);
        g_kvth[p] = h; g_kvtl[p] = l;
        run += v;
    }
}

__global__ void ksumprefix_kernel()
{
    int bh = blockIdx.x, m = threadIdx.x;
    float run = 0.f;
    for (int c = 0; c < NCn; c++) {
        size_t p = ((size_t)bh * NCn + c) * 256 + m;
        float v = g_ksum[p];
        g_ksum[p] = run;
        run += v;
    }
}

// ---------------- attention main (HMMA, R14 proven) ---------------------------
#define ATTN_SMEM 221184
__global__ void __launch_bounds__(256, 1) attn_kernel()
{
    extern __shared__ char smem[];
    const uint32_t sb = smem_u32(smem);
    const int t = threadIdx.x, lane = t & 31, wid = t >> 5;
    const int wm = wid >> 2, wn = wid & 3;
    const int c = blockIdx.x, h = blockIdx.y, b = blockIdx.z;
    const int kvh = h >> 1, bh = b * HKVn + kvh;
    const size_t qoff = (((size_t)(b * Hh + h)) * Ss + (size_t)c * 128) * 256;
    const size_t koff = ((size_t)bh * Ss + (size_t)c * 128) * 256;

    float* den_part = (float*)(smem + 217088);
    float* den2_arr = (float*)(smem + 219136);
    float* den_s    = (float*)(smem + 219648);
    float* ksum_s   = (float*)(smem + 220160);

    ksum_s[t] = g_ksum[((size_t)bh * NCn + c) * 256 + t];

    const int arow = wm * 64 + (lane & 15);
    const int acolB = (lane >> 4) * 16;
    const int brow = wn * 32 + (lane & 7) + ((lane >> 4) & 1) * 8;
    const int bcolB = ((lane >> 3) & 1) * 16;

    const __nv_bfloat16* srcsA[4] = { g_phiqh + qoff, g_phiql + qoff,
                                      g_phikh + koff, g_phikl + koff };
    auto issueA = [&](int s, int kc) {
        uint32_t base = sb + s * 73728;
#pragma unroll
        for (int idx = t; idx < 4096; idx += 256) {
            int tile = idx >> 10, rem = idx & 1023;
            int r = rem >> 3, v = rem & 7;
            cp16(base + tile * 18432 + r * 144 + v * 16,
                 srcsA[tile] + (size_t)r * 256 + kc * 64 + v * 8);
        }
        cp_commit();
    };

    float accP[4][4][4];
#pragma unroll
    for (int i = 0; i < 4; i++)
#pragma unroll
        for (int j = 0; j < 4; j++)
#pragma unroll
            for (int k = 0; k < 4; k++) accP[i][j][k] = 0.f;

    issueA(0, 0); issueA(1, 1);
    for (int kc = 0; kc < 4; kc++) {
        cp_wait1();
        __syncthreads();
        uint32_t bs = sb + (kc & 1) * 73728;
#pragma unroll
        for (int ks = 0; ks < 4; ks++) {
            int kb = ks * 32;
            uint32_t qh[4][4], ql[4][4], bhf[4][2], blf[4][2];
#pragma unroll
            for (int i = 0; i < 4; i++) {
                uint32_t off = (uint32_t)(arow + i * 16) * 144 + kb + acolB;
                ldmx4(qh[i], bs + off);
                ldmx4(ql[i], bs + 18432 + off);
            }
#pragma unroll
            for (int nt = 0; nt < 2; nt++) {
                uint32_t off = (uint32_t)(brow + nt * 16) * 144 + kb + bcolB;
                uint32_t rh[4], rl[4];
                ldmx4(rh, bs + 36864 + off);
                ldmx4(rl, bs + 55296 + off);
                bhf[nt * 2][0] = rh[0]; bhf[nt * 2][1] = rh[1];
                bhf[nt * 2 + 1][0] = rh[2]; bhf[nt * 2 + 1][1] = rh[3];
                blf[nt * 2][0] = rl[0]; blf[nt * 2][1] = rl[1];
                blf[nt * 2 + 1][0] = rl[2]; blf[nt * 2 + 1][1] = rl[3];
            }
#pragma unroll
            for (int i = 0; i < 4; i++)
#pragma unroll
                for (int j = 0; j < 4; j++) {
                    mma16816(accP[i][j], qh[i], bhf[j]);
                    mma16816(accP[i][j], qh[i], blf[j]);
                    mma16816(accP[i][j], ql[i], bhf[j]);
                }
        }
        __syncthreads();
        if (kc + 2 < 4) issueA(kc & 1, kc + 2);
        else cp_commit();
    }

    __nv_bfloat16* Ph = (__nv_bfloat16*)(smem + 147456);
    __nv_bfloat16* Pl = (__nv_bfloat16*)(smem + 182272);
#pragma unroll
    for (int i = 0; i < 4; i++) {
        int r1 = wm * 64 + i * 16 + (lane >> 2);
        float rs1 = 0.f, rs2 = 0.f;
#pragma unroll
        for (int j = 0; j < 4; j++) {
            int n0 = wn * 32 + j * 8 + (lane & 3) * 2;
            float m00 = (n0     <= r1    ) ? accP[i][j][0] : 0.f;
            float m01 = (n0 + 1 <= r1    ) ? accP[i][j][1] : 0.f;
            float m10 = (n0     <= r1 + 8) ? accP[i][j][2] : 0.f;
            float m11 = (n0 + 1 <= r1 + 8) ? accP[i][j][3] : 0.f;
            rs1 += m00 + m01; rs2 += m10 + m11;
            __nv_bfloat16 hh, llv;
            bsplit(m00, hh, llv); Ph[r1 * 136 + n0] = hh;       Pl[r1 * 136 + n0] = llv;
            bsplit(m01, hh, llv); Ph[r1 * 136 + n0 + 1] = hh;   Pl[r1 * 136 + n0 + 1] = llv;
            bsplit(m10, hh, llv); Ph[(r1 + 8) * 136 + n0] = hh; Pl[(r1 + 8) * 136 + n0] = llv;
            bsplit(m11, hh, llv); Ph[(r1 + 8) * 136 + n0 + 1] = hh; Pl[(r1 + 8) * 136 + n0 + 1] = llv;
        }
        rs1 += __shfl_xor_sync(0xffffffffu, rs1, 1);
        rs1 += __shfl_xor_sync(0xffffffffu, rs1, 2);
        rs2 += __shfl_xor_sync(0xffffffffu, rs2, 1);
        rs2 += __shfl_xor_sync(0xffffffffu, rs2, 2);
        if ((lane & 3) == 0) {
            den_part[wn * 128 + r1] = rs1;
            den_part[wn * 128 + r1 + 8] = rs2;
        }
    }
    __syncthreads();
    if (t < 128)
        den_s[t] = den_part[t] + den_part[128 + t] + den_part[256 + t] + den_part[384 + t];

    const __nv_bfloat16* vtsrc[2] = {
        g_vth + (size_t)bh * 128 * 4096 + c * 128,
        g_vtl + (size_t)bh * 128 * 4096 + c * 128 };
#pragma unroll
    for (int idx = t; idx < 4096; idx += 256) {
        int tile = idx >> 11, rem = idx & 2047;
        int r = rem >> 4, v = rem & 15;
        cp16(sb + tile * 34816 + r * 272 + v * 16, vtsrc[tile] + (size_t)r * 4096 + v * 8);
    }
    cp_commit();
    cp_wait0();
    __syncthreads();

    float accO[4][4][4];
#pragma unroll
    for (int i = 0; i < 4; i++)
#pragma unroll
        for (int j = 0; j < 4; j++)
#pragma unroll
            for (int k = 0; k < 4; k++) accO[i][j][k] = 0.f;

#pragma unroll
    for (int ks = 0; ks < 8; ks++) {
        int kb = ks * 32;
        uint32_t ah_[4][4], al_[4][4], bhf[4][2], blf[4][2];
#pragma unroll
        for (int i = 0; i < 4; i++) {
            uint32_t off = (uint32_t)(arow + i * 16) * 272 + kb + acolB;
            ldmx4(ah_[i], sb + 147456 + off);
            ldmx4(al_[i], sb + 182272 + off);
        }
#pragma unroll
        for (int nt = 0; nt < 2; nt++) {
            uint32_t off = (uint32_t)(brow + nt * 16) * 272 + kb + bcolB;
            uint32_t rh[4], rl[4];
            ldmx4(rh, sb + off);
            ldmx4(rl, sb + 34816 + off);
            bhf[nt * 2][0] = rh[0]; bhf[nt * 2][1] = rh[1];
            bhf[nt * 2 + 1][0] = rh[2]; bhf[nt * 2 + 1][1] = rh[3];
            blf[nt * 2][0] = rl[0]; blf[nt * 2][1] = rl[1];
            blf[nt * 2 + 1][0] = rl[2]; blf[nt * 2 + 1][1] = rl[3];
        }
#pragma unroll
        for (int i = 0; i < 4; i++)
#pragma unroll
            for (int j = 0; j < 4; j++) {
                mma16816(accO[i][j], ah_[i], bhf[j]);
                mma16816(accO[i][j], ah_[i], blf[j]);
                mma16816(accO[i][j], al_[i], bhf[j]);
            }
    }
    __syncthreads();

    const __nv_bfloat16* srcsC[4] = { g_phiqh + qoff, g_phiql + qoff,
        g_kvth + ((size_t)bh * NCn + c) * 32768,
        g_kvtl + ((size_t)bh * NCn + c) * 32768 };
    auto issueC = [&](int s, int kc) {
        uint32_t base = sb + s * 73728;
#pragma unroll
        for (int idx = t; idx < 4096; idx += 256) {
            int tile = idx >> 10, rem = idx & 1023;
            int r = rem >> 3, v = rem & 7;
            cp16(base + tile * 18432 + r * 144 + v * 16,
                 srcsC[tile] + (size_t)r * 256 + kc * 64 + v * 8);
        }
        cp_commit();
    };

    float den2r = 0.f;
    issueC(0, 0); issueC(1, 1);
    for (int kc = 0; kc < 4; kc++) {
        cp_wait1();
        __syncthreads();
        uint32_t bs = sb + (kc & 1) * 73728;
#pragma unroll
        for (int ks = 0; ks < 4; ks++) {
            int kb = ks * 32;
            uint32_t qh[4][4], ql[4][4], bhf[4][2], blf[4][2];
#pragma unroll
            for (int i = 0; i < 4; i++) {
                uint32_t off = (uint32_t)(arow + i * 16) * 144 + kb + acolB;
                ldmx4(qh[i], bs + off);
                ldmx4(ql[i], bs + 18432 + off);
            }
#pragma unroll
            for (int nt = 0; nt < 2; nt++) {
                uint32_t off = (uint32_t)(brow + nt * 16) * 144 + kb + bcolB;
                uint32_t rh[4], rl[4];
                ldmx4(rh, bs + 36864 + off);
                ldmx4(rl, bs + 55296 + off);
                bhf[nt * 2][0] = rh[0]; bhf[nt * 2][1] = rh[1];
                bhf[nt * 2 + 1][0] = rh[2]; bhf[nt * 2 + 1][1] = rh[3];
                blf[nt * 2][0] = rl[0]; blf[nt * 2][1] = rl[1];
                blf[nt * 2 + 1][0] = rl[2]; blf[nt * 2 + 1][1] = rl[3];
            }
#pragma unroll
            for (int i = 0; i < 4; i++)
#pragma unroll
                for (int j = 0; j < 4; j++) {
                    mma16816(accO[i][j], qh[i], bhf[j]);
                    mma16816(accO[i][j], qh[i], blf[j]);
                    mma16816(accO[i][j], ql[i], bhf[j]);
                }
        }
        if (t < 128) {
            const __nv_bfloat16* qh_e = (const __nv_bfloat16*)(smem + (kc & 1) * 73728);
            const __nv_bfloat16* ql_e = qh_e + 9216;
            for (int mm = 0; mm < 64; mm++)
                den2r += (__bfloat162float(qh_e[t * 72 + mm]) +
                          __bfloat162float(ql_e[t * 72 + mm])) * ksum_s[kc * 64 + mm];
        }
        __syncthreads();
        if (kc + 2 < 4) issueC(kc & 1, kc + 2);
        else cp_commit();
    }
    if (t < 128) den2_arr[t] = den2r;
    __syncthreads();

#pragma unroll
    for (int i = 0; i < 4; i++) {
        int r1 = wm * 64 + i * 16 + (lane >> 2);
        float dn1 = den_s[r1] + den2_arr[r1] + 1e-6f;
        float dn2 = den_s[r1 + 8] + den2_arr[r1 + 8] + 1e-6f;
        int s1 = c * 128 + r1;
#pragma unroll
        for (int j = 0; j < 4; j++) {
            int n0 = wn * 32 + j * 8 + (lane & 3) * 2;
            float v00 = accO[i][j][0] / dn1, v01 = accO[i][j][1] / dn1;
            float v10 = accO[i][j][2] / dn2, v11 = accO[i][j][3] / dn2;
            size_t o1 = ((size_t)b * Ss + s1) * 2048 + h * 128 + n0;
            size_t o2 = ((size_t)b * Ss + s1 + 8) * 2048 + h * 128 + n0;
            __nv_bfloat16 hh, llv;
            bsplit(v00, hh, llv); g_ah[o1] = hh;     g_al[o1] = llv;
            bsplit(v01, hh, llv); g_ah[o1 + 1] = hh; g_al[o1 + 1] = llv;
            bsplit(v10, hh, llv); g_ah[o2] = hh;     g_al[o2] = llv;
            bsplit(v11, hh, llv); g_ah[o2 + 1] = hh; g_al[o2 + 1] = llv;
        }
    }
}

// ---------------- launch ------------------------------------------------------
extern "C" void kernel_launch(void* const* d_in, const int* in_sizes, int n_in,
                              void* d_out, int out_size)
{
    const float* hs   = (const float*)d_in[0];
    const float* cosp = (const float*)d_in[1];
    const float* sinp = (const float*)d_in[2];
    const float* wq   = (const float*)d_in[3];
    const float* wk   = (const float*)d_in[4];
    const float* wv   = (const float*)d_in[5];
    const float* wo   = (const float*)d_in[6];
    const float* proj = (const float*)d_in[7];
    float* out = (float*)d_out;

    __nv_bfloat16 *ah, *al, *wqh, *wql, *wkh, *wkl, *wvh, *wvl, *woh, *wol;
    __nv_bfloat16 *projh, *projl;
    cudaGetSymbolAddress((void**)&ah,  g_ah);
    cudaGetSymbolAddress((void**)&al,  g_al);
    cudaGetSymbolAddress((void**)&wqh, g_wqh);
    cudaGetSymbolAddress((void**)&wql, g_wql);
    cudaGetSymbolAddress((void**)&wkh, g_wkh);
    cudaGetSymbolAddress((void**)&wkl, g_wkl);
    cudaGetSymbolAddress((void**)&wvh, g_wvh);
    cudaGetSymbolAddress((void**)&wvl, g_wvl);
    cudaGetSymbolAddress((void**)&woh, g_woh);
    cudaGetSymbolAddress((void**)&wol, g_wol);
    cudaGetSymbolAddress((void**)&projh, g_projh);
    cudaGetSymbolAddress((void**)&projl, g_projl);

    cudaFuncSetAttribute(featmap_hmma, cudaFuncAttributeMaxDynamicSharedMemorySize, FM_SMEM);
    cudaFuncSetAttribute(attn_kernel,  cudaFuncAttributeMaxDynamicSharedMemorySize, ATTN_SMEM);
    cudaFuncSetAttribute(hmma_gemm,    cudaFuncAttributeMaxDynamicSharedMemorySize, 2 * STG_BYTES);
    cudaFuncSetAttribute(hmma_qkv,     cudaFuncAttributeMaxDynamicSharedMemorySize, 2 * STG_BYTES);

    // splits
    split_kernel<<<16384, 256>>>(hs, ah, al, 4194304);
    split_kernel<<<4096,  256>>>(wq, wqh, wql, 1048576);
    split_kernel<<<2048,  256>>>(wk, wkh, wkl, 524288);
    split_kernel<<<2048,  256>>>(wv, wvh, wvl, 524288);
    split_kernel<<<4096,  256>>>(wo, woh, wol, 1048576);
    split_kernel<<<32,    256>>>(proj, projh, projl, 8192);

    // fused QKV projection (R10 config; V blocks also emit vth/vtl)
    hmma_qkv<<<dim3(32, 64), 256, 2 * STG_BYTES>>>();

    // feature maps (q + k merged; 2-pass proj, 2 CTAs/SM)
    featmap_hmma<<<3072, 256, FM_SMEM>>>(cosp, sinp);
    // exp + hi/lo split + chunk colsums (global max folded in per-block)
    expk_ksum_kernel<<<dim3(NCn, Bb * HKVn), 256>>>();

    // chunk states (transposed [d,m] output; prefix writes bf16 directly)
    kvchunk_kernel<<<dim3(2, NCn, Bb * HKVn), 256>>>();
    kvprefix_kernel<<<dim3(128, Bb * HKVn), 256>>>();
    ksumprefix_kernel<<<Bb * HKVn, 256>>>();

    // attention (R14 proven: 128 q-rows, double-buffered, 1 CTA/SM)
    attn_kernel<<<dim3(NCn, Hh, Bb), 256, ATTN_SMEM>>>();

    // output projection (R10 config)
    hmma_gemm<<<dim3(16, 64), 256, 2 * STG_BYTES>>>(ah, al, woh, wol, out, 2048, 0, 0);
}